// round 2
// baseline (speedup 1.0000x reference)
#include <cuda_runtime.h>
#include <cuda_bf16.h>
#include <math.h>

#define FULL_MASK 0xffffffffu

// Problem constants (fixed by the reference setup)
#define BATCH   32
#define DIM     4096
#define NQ      32
#define NKV     8
#define HD      128
#define QKV_N   6144   // 4096 q + 1024 k + 1024 v
#define REP     4      // NQ / NKV

// Scratch (device globals; no allocation allowed)
__device__ float g_qkv[BATCH * QKV_N];   // per batch: [q(4096) | k(1024) | v(1024)]
__device__ float g_att[BATCH * DIM];     // attention output, pre-wo

// ---------------- packed fp32x2 helpers (Blackwell) ----------------
__device__ __forceinline__ unsigned long long pack2(float lo, float hi) {
    unsigned long long r;
    asm("mov.b64 %0, {%1, %2};" : "=l"(r) : "f"(lo), "f"(hi));
    return r;
}
__device__ __forceinline__ void fma2(unsigned long long& d, unsigned long long a, unsigned long long b) {
    asm("fma.rn.f32x2 %0, %1, %2, %0;" : "+l"(d) : "l"(a), "l"(b));
}
__device__ __forceinline__ float2 unpack2(unsigned long long v) {
    float lo, hi;
    asm("mov.b64 {%0, %1}, %2;" : "=f"(lo), "=f"(hi) : "l"(v));
    return make_float2(lo, hi);
}

// ---------------- Generic skinny GEMM tile ----------------
// C[m, ccol0 + c] = sum_k A[m, k] * W[wrow0 + c, k],  M = 32 rows, 64 cols per block.
// 128 threads: col c = tid&31 (owns c and c+32), rows 8*(tid>>5) .. +7 as 4 f32x2 pairs.
__device__ __forceinline__ void gemm_tile(const float* __restrict__ A,
                                          const float* __restrict__ W,
                                          float* __restrict__ C,
                                          int K, int ldc, int wrow0, int ccol0)
{
    __shared__ float As[32][34];   // [kk][m], pad 34 keeps 8B alignment for m-pairs
    __shared__ float Ws[32][65];   // [kk][n]

    const int tid   = threadIdx.x;        // 0..127
    const int c     = tid & 31;
    const int rbase = (tid >> 5) << 3;    // 0,8,16,24

    unsigned long long acc[4][2];
#pragma unroll
    for (int p = 0; p < 4; p++) { acc[p][0] = 0ull; acc[p][1] = 0ull; }

    for (int k0 = 0; k0 < K; k0 += 32) {
        // Fill A tile: 32 rows x 32 k = 1024 elems
#pragma unroll
        for (int j = 0; j < 8; j++) {
            int e = tid + j * 128;
            int kk = e & 31, m = e >> 5;
            As[kk][m] = A[(size_t)m * K + k0 + kk];
        }
        // Fill W tile: 64 rows x 32 k = 2048 elems
#pragma unroll
        for (int j = 0; j < 16; j++) {
            int e = tid + j * 128;
            int kk = e & 31, n = e >> 5;
            Ws[kk][n] = W[(size_t)(wrow0 + n) * K + k0 + kk];
        }
        __syncthreads();

#pragma unroll
        for (int kk = 0; kk < 32; kk++) {
            const unsigned long long* ap =
                reinterpret_cast<const unsigned long long*>(&As[kk][rbase]);
            unsigned long long a0 = ap[0], a1 = ap[1], a2 = ap[2], a3 = ap[3];
            float w0 = Ws[kk][c];
            float w1 = Ws[kk][c + 32];
            unsigned long long W0 = pack2(w0, w0);
            unsigned long long W1 = pack2(w1, w1);
            fma2(acc[0][0], a0, W0); fma2(acc[1][0], a1, W0);
            fma2(acc[2][0], a2, W0); fma2(acc[3][0], a3, W0);
            fma2(acc[0][1], a0, W1); fma2(acc[1][1], a1, W1);
            fma2(acc[2][1], a2, W1); fma2(acc[3][1], a3, W1);
        }
        __syncthreads();
    }

#pragma unroll
    for (int p = 0; p < 4; p++) {
#pragma unroll
        for (int cc = 0; cc < 2; cc++) {
            float2 v = unpack2(acc[p][cc]);
            int m   = rbase + 2 * p;
            int col = ccol0 + c + 32 * cc;
            C[(size_t)m * ldc + col]       = v.x;
            C[(size_t)(m + 1) * ldc + col] = v.y;
        }
    }
}

// ---------------- QKV projection (one launch, pointer dispatch per block) ----------------
__global__ void gemm_qkv_kernel(const float* __restrict__ x,
                                const float* __restrict__ wq,
                                const float* __restrict__ wk,
                                const float* __restrict__ wv)
{
    int n0 = blockIdx.x * 64;          // 0 .. 6080
    const float* W;
    int wrow0;
    if (n0 < 4096)      { W = wq; wrow0 = n0; }
    else if (n0 < 5120) { W = wk; wrow0 = n0 - 4096; }
    else                { W = wv; wrow0 = n0 - 5120; }
    gemm_tile(x, W, g_qkv, DIM, QKV_N, wrow0, n0);
}

// ---------------- Output projection ----------------
__global__ void gemm_o_kernel(const float* __restrict__ wo, float* __restrict__ out)
{
    int n0 = blockIdx.x * 64;
    gemm_tile(g_att, wo, out, DIM, DIM, n0, n0);
}

// ---------------- RoPE on q (4096 cols) + k (1024 cols) per batch ----------------
__global__ void rope_kernel(const float* __restrict__ cosv, const float* __restrict__ sinv)
{
    int idx = blockIdx.x * 256 + threadIdx.x;   // pair index, total 32*2560
    if (idx >= BATCH * 2560) return;
    int b = idx / 2560;
    int r = idx - b * 2560;
    int col = r * 2;                   // 0..5118 (q then k region)
    int d2 = (col & (HD - 1)) >> 1;    // 0..63
    float c = cosv[d2], s = sinv[d2];
    float2* p = reinterpret_cast<float2*>(&g_qkv[(size_t)b * QKV_N + col]);
    float2 t = *p;
    float r0 = t.x * c - t.y * s;
    float r1 = t.x * s + t.y * c;
    *p = make_float2(r0, r1);
}

// ---------------- Attention: one block per (kv-head g, batch b) ----------------
__global__ void attn_kernel(const float* __restrict__ cache_k,
                            const float* __restrict__ cache_v,
                            const int* __restrict__ sp_ptr,
                            int max_seq)
{
    const int g    = blockIdx.x;      // 0..7
    const int b    = blockIdx.y;      // 0..31
    const int tid  = threadIdx.x;     // 0..255
    const int lane = tid & 31;
    const int w    = tid >> 5;        // 0..7
    const int sp   = *sp_ptr;
    const int T    = sp + 1;          // <= 2048

    __shared__ float sc[REP][2048];
    __shared__ float q4s[REP][HD];
    __shared__ float red[8];
    __shared__ float rmax4[REP];
    __shared__ float rsum4[REP];

    // load the 4 q heads of this kv group
    for (int i = tid; i < REP * HD; i += 256) {
        int r = i >> 7, d = i & (HD - 1);
        q4s[r][d] = g_qkv[(size_t)b * QKV_N + (g * REP + r) * HD + d];
    }
    __syncthreads();

    // per-lane q registers: 4 contiguous dims per rep
    float4 q0 = reinterpret_cast<const float4*>(q4s[0])[lane];
    float4 q1 = reinterpret_cast<const float4*>(q4s[1])[lane];
    float4 q2 = reinterpret_cast<const float4*>(q4s[2])[lane];
    float4 q3 = reinterpret_cast<const float4*>(q4s[3])[lane];

    const float* knew = &g_qkv[(size_t)b * QKV_N + 4096 + g * HD];
    const float* vnew = &g_qkv[(size_t)b * QKV_N + 5120 + g * HD];
    const float scale = 0.08838834764831845f;  // 1/sqrt(128)

    // ---- scores: warp-per-t, float4 coalesced K reads ----
    for (int t = w; t < sp; t += 8) {
        const float* kp = &cache_k[(((size_t)b * max_seq + t) * NKV + g) * HD];
        float4 kv = reinterpret_cast<const float4*>(kp)[lane];
        float p0 = q0.x * kv.x + q0.y * kv.y + q0.z * kv.z + q0.w * kv.w;
        float p1 = q1.x * kv.x + q1.y * kv.y + q1.z * kv.z + q1.w * kv.w;
        float p2 = q2.x * kv.x + q2.y * kv.y + q2.z * kv.z + q2.w * kv.w;
        float p3 = q3.x * kv.x + q3.y * kv.y + q3.z * kv.z + q3.w * kv.w;
#pragma unroll
        for (int off = 16; off; off >>= 1) {
            p0 += __shfl_xor_sync(FULL_MASK, p0, off);
            p1 += __shfl_xor_sync(FULL_MASK, p1, off);
            p2 += __shfl_xor_sync(FULL_MASK, p2, off);
            p3 += __shfl_xor_sync(FULL_MASK, p3, off);
        }
        if (lane == 0) {
            sc[0][t] = p0 * scale; sc[1][t] = p1 * scale;
            sc[2][t] = p2 * scale; sc[3][t] = p3 * scale;
        }
    }
    // t == sp uses the freshly projected (and RoPE'd) k
    if (w == 0) {
        float4 kv = reinterpret_cast<const float4*>(knew)[lane];
        float p0 = q0.x * kv.x + q0.y * kv.y + q0.z * kv.z + q0.w * kv.w;
        float p1 = q1.x * kv.x + q1.y * kv.y + q1.z * kv.z + q1.w * kv.w;
        float p2 = q2.x * kv.x + q2.y * kv.y + q2.z * kv.z + q2.w * kv.w;
        float p3 = q3.x * kv.x + q3.y * kv.y + q3.z * kv.z + q3.w * kv.w;
#pragma unroll
        for (int off = 16; off; off >>= 1) {
            p0 += __shfl_xor_sync(FULL_MASK, p0, off);
            p1 += __shfl_xor_sync(FULL_MASK, p1, off);
            p2 += __shfl_xor_sync(FULL_MASK, p2, off);
            p3 += __shfl_xor_sync(FULL_MASK, p3, off);
        }
        if (lane == 0) {
            sc[0][sp] = p0 * scale; sc[1][sp] = p1 * scale;
            sc[2][sp] = p2 * scale; sc[3][sp] = p3 * scale;
        }
    }
    __syncthreads();

    // ---- softmax (max, exp, sum) per rep ----
    for (int r = 0; r < REP; r++) {
        float m = -3.0e38f;
        for (int t = tid; t < T; t += 256) m = fmaxf(m, sc[r][t]);
#pragma unroll
        for (int off = 16; off; off >>= 1) m = fmaxf(m, __shfl_xor_sync(FULL_MASK, m, off));
        if (lane == 0) red[w] = m;
        __syncthreads();
        if (tid == 0) {
            float mm = red[0];
            for (int i = 1; i < 8; i++) mm = fmaxf(mm, red[i]);
            rmax4[r] = mm;
        }
        __syncthreads();
        m = rmax4[r];

        float s = 0.f;
        for (int t = tid; t < T; t += 256) {
            float e = __expf(sc[r][t] - m);
            sc[r][t] = e;
            s += e;
        }
#pragma unroll
        for (int off = 16; off; off >>= 1) s += __shfl_xor_sync(FULL_MASK, s, off);
        if (lane == 0) red[w] = s;
        __syncthreads();
        if (tid == 0) {
            float ss = 0.f;
            for (int i = 0; i < 8; i++) ss += red[i];
            rsum4[r] = ss;
        }
        __syncthreads();
    }

    // ---- A @ V: thread owns (rh, d) and (rh+2, d), coalesced V reads ----
    const int d  = tid & (HD - 1);
    const int rh = tid >> 7;          // 0 or 1
    float a0 = 0.f, a1 = 0.f;
#pragma unroll 4
    for (int t = 0; t < sp; t++) {
        float v = cache_v[(((size_t)b * max_seq + t) * NKV + g) * HD + d];
        a0 += sc[rh][t] * v;
        a1 += sc[rh + 2][t] * v;
    }
    {
        float v = vnew[d];
        a0 += sc[rh][sp] * v;
        a1 += sc[rh + 2][sp] * v;
    }
    float o0 = a0 / rsum4[rh];
    float o1 = a1 / rsum4[rh + 2];
    g_att[(size_t)b * DIM + (g * REP + rh) * HD + d]       = o0;
    g_att[(size_t)b * DIM + (g * REP + rh + 2) * HD + d]   = o1;
}

// ---------------- launch ----------------
extern "C" void kernel_launch(void* const* d_in, const int* in_sizes, int n_in,
                              void* d_out, int out_size)
{
    const float* x  = (const float*)d_in[0];
    const float* wq = (const float*)d_in[1];
    const float* wk = (const float*)d_in[2];
    const float* wv = (const float*)d_in[3];
    const float* wo = (const float*)d_in[4];
    const float* fc = (const float*)d_in[5];
    const float* fs = (const float*)d_in[6];
    const float* ck = (const float*)d_in[7];
    const float* cv = (const float*)d_in[8];
    const int*   sp = (const int*)d_in[9];

    int max_seq = in_sizes[7] / (BATCH * NKV * HD);

    gemm_qkv_kernel<<<QKV_N / 64, 128>>>(x, wq, wk, wv);
    rope_kernel<<<(BATCH * 2560 + 255) / 256, 256>>>(fc, fs);
    attn_kernel<<<dim3(NKV, BATCH), 256>>>(ck, cv, sp, max_seq);
    gemm_o_kernel<<<DIM / 64, 128>>>(wo, (float*)d_out);
}

// round 4
// speedup vs baseline: 2.6916x; 2.6916x over previous
#include <cuda_runtime.h>
#include <cuda_bf16.h>
#include <math.h>

#define FULL_MASK 0xffffffffu

#define BATCH   32
#define DIM     4096
#define NQ      32
#define NKV     8
#define HD      128
#define QKV_N   6144
#define REP     4
#define KSPLIT  8
#define KLEN    (DIM / KSPLIT)   // 512

// Scratch (device globals; no allocation allowed)
__device__ float g_qkv[BATCH * QKV_N];                    // post-reduce, post-RoPE
__device__ float g_att[BATCH * DIM];                      // attention output, pre-wo
__device__ float g_part_qkv[KSPLIT][BATCH][QKV_N];        // split-K partials
__device__ float g_part_o[KSPLIT][BATCH][DIM];

// ---------------- packed fp32x2 helpers (Blackwell) ----------------
__device__ __forceinline__ unsigned long long pack2(float lo, float hi) {
    unsigned long long r;
    asm("mov.b64 %0, {%1, %2};" : "=l"(r) : "f"(lo), "f"(hi));
    return r;
}
__device__ __forceinline__ void fma2(unsigned long long& d, unsigned long long a, unsigned long long b) {
    asm("fma.rn.f32x2 %0, %1, %2, %0;" : "+l"(d) : "l"(a), "l"(b));
}
__device__ __forceinline__ float2 unpack2(unsigned long long v) {
    float lo, hi;
    asm("mov.b64 {%0, %1}, %2;" : "=f"(lo), "=f"(hi) : "l"(v));
    return make_float2(lo, hi);
}

// ---------------- Split-K skinny GEMM tile ----------------
// Cpart[m, ccol0+c] = sum_{k in [kbeg, kbeg+KLEN)} A[m,k] * W[wrow0+c, k]
// M = 32 rows, 64 cols per block, 128 threads.
__device__ __forceinline__ void gemm_tile(const float* __restrict__ A,
                                          const float* __restrict__ W,
                                          float* __restrict__ C,
                                          int K, int ldc, int wrow0, int ccol0,
                                          int kbeg)
{
    __shared__ float As[32][34];
    __shared__ float Ws[32][65];

    const int tid   = threadIdx.x;
    const int c     = tid & 31;
    const int rbase = (tid >> 5) << 3;

    unsigned long long acc[4][2];
#pragma unroll
    for (int p = 0; p < 4; p++) { acc[p][0] = 0ull; acc[p][1] = 0ull; }

    for (int k0 = kbeg; k0 < kbeg + KLEN; k0 += 32) {
#pragma unroll
        for (int j = 0; j < 8; j++) {
            int e = tid + j * 128;
            int kk = e & 31, m = e >> 5;
            As[kk][m] = A[(size_t)m * K + k0 + kk];
        }
#pragma unroll
        for (int j = 0; j < 16; j++) {
            int e = tid + j * 128;
            int kk = e & 31, n = e >> 5;
            Ws[kk][n] = W[(size_t)(wrow0 + n) * K + k0 + kk];
        }
        __syncthreads();

#pragma unroll
        for (int kk = 0; kk < 32; kk++) {
            const unsigned long long* ap =
                reinterpret_cast<const unsigned long long*>(&As[kk][rbase]);
            unsigned long long a0 = ap[0], a1 = ap[1], a2 = ap[2], a3 = ap[3];
            float w0 = Ws[kk][c];
            float w1 = Ws[kk][c + 32];
            unsigned long long W0 = pack2(w0, w0);
            unsigned long long W1 = pack2(w1, w1);
            fma2(acc[0][0], a0, W0); fma2(acc[1][0], a1, W0);
            fma2(acc[2][0], a2, W0); fma2(acc[3][0], a3, W0);
            fma2(acc[0][1], a0, W1); fma2(acc[1][1], a1, W1);
            fma2(acc[2][1], a2, W1); fma2(acc[3][1], a3, W1);
        }
        __syncthreads();
    }

#pragma unroll
    for (int p = 0; p < 4; p++) {
#pragma unroll
        for (int cc = 0; cc < 2; cc++) {
            float2 v = unpack2(acc[p][cc]);
            int m   = rbase + 2 * p;
            int col = ccol0 + c + 32 * cc;
            C[(size_t)m * ldc + col]       = v.x;
            C[(size_t)(m + 1) * ldc + col] = v.y;
        }
    }
}

// ---------------- QKV projection: grid (96, KSPLIT) ----------------
__global__ void gemm_qkv_kernel(const float* __restrict__ x,
                                const float* __restrict__ wq,
                                const float* __restrict__ wk,
                                const float* __restrict__ wv)
{
    int n0 = blockIdx.x * 64;
    int kbeg = blockIdx.y * KLEN;
    const float* W;
    int wrow0;
    if (n0 < 4096)      { W = wq; wrow0 = n0; }
    else if (n0 < 5120) { W = wk; wrow0 = n0 - 4096; }
    else                { W = wv; wrow0 = n0 - 5120; }
    gemm_tile(x, W, &g_part_qkv[blockIdx.y][0][0], DIM, QKV_N, wrow0, n0, kbeg);
}

// ---------------- Output projection: grid (64, KSPLIT) ----------------
__global__ void gemm_o_kernel(const float* __restrict__ wo)
{
    int n0 = blockIdx.x * 64;
    int kbeg = blockIdx.y * KLEN;
    gemm_tile(g_att, wo, &g_part_o[blockIdx.y][0][0], DIM, DIM, n0, n0, kbeg);
}

// ---------------- QKV reduce + fused RoPE ----------------
__global__ void reduce_qkv_rope(const float* __restrict__ cosv,
                                const float* __restrict__ sinv)
{
    int idx = blockIdx.x * 256 + threadIdx.x;       // pair index
    if (idx >= BATCH * (QKV_N / 2)) return;
    int b  = idx / (QKV_N / 2);
    int pr = idx - b * (QKV_N / 2);
    int col = pr * 2;

    float sx = 0.f, sy = 0.f;
#pragma unroll
    for (int ks = 0; ks < KSPLIT; ks++) {
        float2 v = *reinterpret_cast<const float2*>(&g_part_qkv[ks][b][col]);
        sx += v.x; sy += v.y;
    }
    float2 o;
    if (col < 5120) {   // q + k get RoPE
        int d2 = (col & (HD - 1)) >> 1;
        float c = cosv[d2], s = sinv[d2];
        o.x = sx * c - sy * s;
        o.y = sx * s + sy * c;
    } else {
        o.x = sx; o.y = sy;
    }
    *reinterpret_cast<float2*>(&g_qkv[(size_t)b * QKV_N + col]) = o;
}

// ---------------- Output reduce -> d_out ----------------
__global__ void reduce_o(float* __restrict__ out)
{
    int idx = blockIdx.x * 256 + threadIdx.x;       // pair index
    if (idx >= BATCH * (DIM / 2)) return;
    int b  = idx / (DIM / 2);
    int pr = idx - b * (DIM / 2);
    int col = pr * 2;
    float sx = 0.f, sy = 0.f;
#pragma unroll
    for (int ks = 0; ks < KSPLIT; ks++) {
        float2 v = *reinterpret_cast<const float2*>(&g_part_o[ks][b][col]);
        sx += v.x; sy += v.y;
    }
    *reinterpret_cast<float2*>(&out[(size_t)b * DIM + col]) = make_float2(sx, sy);
}

// ---------------- Attention: block per (kv-head g, batch b), 512 threads ----------------
__global__ void attn_kernel(const float* __restrict__ cache_k,
                            const float* __restrict__ cache_v,
                            const int* __restrict__ sp_ptr,
                            int max_seq)
{
    const int g    = blockIdx.x;
    const int b    = blockIdx.y;
    const int tid  = threadIdx.x;     // 0..511
    const int lane = tid & 31;
    const int w    = tid >> 5;        // 0..15
    const int sp   = *sp_ptr;
    const int T    = sp + 1;

    __shared__ float sc[REP][2048];
    __shared__ float q4s[REP][HD];
    __shared__ float red[16];
    __shared__ float rmax4[REP];
    __shared__ float rsum4[REP];

    for (int i = tid; i < REP * HD; i += 512) {
        int r = i >> 7, d = i & (HD - 1);
        q4s[r][d] = g_qkv[(size_t)b * QKV_N + (g * REP + r) * HD + d];
    }
    __syncthreads();

    float4 q0 = reinterpret_cast<const float4*>(q4s[0])[lane];
    float4 q1 = reinterpret_cast<const float4*>(q4s[1])[lane];
    float4 q2 = reinterpret_cast<const float4*>(q4s[2])[lane];
    float4 q3 = reinterpret_cast<const float4*>(q4s[3])[lane];

    const float* knew = &g_qkv[(size_t)b * QKV_N + 4096 + g * HD];
    const float* vnew = &g_qkv[(size_t)b * QKV_N + 5120 + g * HD];
    const float scale = 0.08838834764831845f;

    // ---- scores: warp-per-t across 16 warps ----
    for (int t = w; t < sp; t += 16) {
        const float* kp = &cache_k[(((size_t)b * max_seq + t) * NKV + g) * HD];
        float4 kv = reinterpret_cast<const float4*>(kp)[lane];
        float p0 = q0.x * kv.x + q0.y * kv.y + q0.z * kv.z + q0.w * kv.w;
        float p1 = q1.x * kv.x + q1.y * kv.y + q1.z * kv.z + q1.w * kv.w;
        float p2 = q2.x * kv.x + q2.y * kv.y + q2.z * kv.z + q2.w * kv.w;
        float p3 = q3.x * kv.x + q3.y * kv.y + q3.z * kv.z + q3.w * kv.w;
#pragma unroll
        for (int off = 16; off; off >>= 1) {
            p0 += __shfl_xor_sync(FULL_MASK, p0, off);
            p1 += __shfl_xor_sync(FULL_MASK, p1, off);
            p2 += __shfl_xor_sync(FULL_MASK, p2, off);
            p3 += __shfl_xor_sync(FULL_MASK, p3, off);
        }
        if (lane == 0) {
            sc[0][t] = p0 * scale; sc[1][t] = p1 * scale;
            sc[2][t] = p2 * scale; sc[3][t] = p3 * scale;
        }
    }
    if (w == 0) {   // t == sp from freshly projected k
        float4 kv = reinterpret_cast<const float4*>(knew)[lane];
        float p0 = q0.x * kv.x + q0.y * kv.y + q0.z * kv.z + q0.w * kv.w;
        float p1 = q1.x * kv.x + q1.y * kv.y + q1.z * kv.z + q1.w * kv.w;
        float p2 = q2.x * kv.x + q2.y * kv.y + q2.z * kv.z + q2.w * kv.w;
        float p3 = q3.x * kv.x + q3.y * kv.y + q3.z * kv.z + q3.w * kv.w;
#pragma unroll
        for (int off = 16; off; off >>= 1) {
            p0 += __shfl_xor_sync(FULL_MASK, p0, off);
            p1 += __shfl_xor_sync(FULL_MASK, p1, off);
            p2 += __shfl_xor_sync(FULL_MASK, p2, off);
            p3 += __shfl_xor_sync(FULL_MASK, p3, off);
        }
        if (lane == 0) {
            sc[0][sp] = p0 * scale; sc[1][sp] = p1 * scale;
            sc[2][sp] = p2 * scale; sc[3][sp] = p3 * scale;
        }
    }
    __syncthreads();

    // ---- softmax per rep ----
    for (int r = 0; r < REP; r++) {
        float m = -3.0e38f;
        for (int t = tid; t < T; t += 512) m = fmaxf(m, sc[r][t]);
#pragma unroll
        for (int off = 16; off; off >>= 1) m = fmaxf(m, __shfl_xor_sync(FULL_MASK, m, off));
        if (lane == 0) red[w] = m;
        __syncthreads();
        if (tid == 0) {
            float mm = red[0];
            for (int i = 1; i < 16; i++) mm = fmaxf(mm, red[i]);
            rmax4[r] = mm;
        }
        __syncthreads();
        m = rmax4[r];

        float s = 0.f;
        for (int t = tid; t < T; t += 512) {
            float e = __expf(sc[r][t] - m);
            sc[r][t] = e;
            s += e;
        }
#pragma unroll
        for (int off = 16; off; off >>= 1) s += __shfl_xor_sync(FULL_MASK, s, off);
        if (lane == 0) red[w] = s;
        __syncthreads();
        if (tid == 0) {
            float ss = 0.f;
            for (int i = 0; i < 16; i++) ss += red[i];
            rsum4[r] = ss;
        }
        __syncthreads();
    }

    // ---- A @ V: 512 threads = 128 dims x 4 reps ----
    const int d = tid & (HD - 1);
    const int r = tid >> 7;           // 0..3
    float a = 0.f;
#pragma unroll 8
    for (int t = 0; t < sp; t++) {
        float v = cache_v[(((size_t)b * max_seq + t) * NKV + g) * HD + d];
        a += sc[r][t] * v;
    }
    a += sc[r][sp] * vnew[d];
    g_att[(size_t)b * DIM + (g * REP + r) * HD + d] = a / rsum4[r];
}

// ---------------- launch ----------------
extern "C" void kernel_launch(void* const* d_in, const int* in_sizes, int n_in,
                              void* d_out, int out_size)
{
    const float* x  = (const float*)d_in[0];
    const float* wq = (const float*)d_in[1];
    const float* wk = (const float*)d_in[2];
    const float* wv = (const float*)d_in[3];
    const float* wo = (const float*)d_in[4];
    const float* fc = (const float*)d_in[5];
    const float* fs = (const float*)d_in[6];
    const float* ck = (const float*)d_in[7];
    const float* cv = (const float*)d_in[8];
    const int*   sp = (const int*)d_in[9];

    int max_seq = in_sizes[7] / (BATCH * NKV * HD);

    gemm_qkv_kernel<<<dim3(QKV_N / 64, KSPLIT), 128>>>(x, wq, wk, wv);
    reduce_qkv_rope<<<(BATCH * (QKV_N / 2) + 255) / 256, 256>>>(fc, fs);
    attn_kernel<<<dim3(NKV, BATCH), 512>>>(ck, cv, sp, max_seq);
    gemm_o_kernel<<<dim3(DIM / 64, KSPLIT), 128>>>(wo);
    reduce_o<<<(BATCH * (DIM / 2) + 255) / 256, 256>>>((float*)d_out);
}